// round 1
// baseline (speedup 1.0000x reference)
#include <cuda_runtime.h>
#include <cuda_fp16.h>
#include <cstdint>

#define HW 128
#define CH 128

// Folded effective weights [tap][co][ci] (fp16) and bias [co]
__device__ __half d_Wg[9 * 128 * 128];
__device__ float  d_Beff[128];

// For each output blade m and input blade k: the unique conv index j and sign.
__constant__ int cJ[8][8] = {
  {0,1,2,3,4,5,6,7},
  {1,0,4,6,2,7,3,5},
  {2,4,0,5,1,3,7,6},
  {3,6,5,0,7,2,1,4},
  {4,2,1,7,0,6,5,3},
  {5,7,3,2,6,0,4,1},
  {6,3,7,1,5,4,0,2},
  {7,5,6,4,3,1,2,0}};
__constant__ float cS[8][8] = {
  { 1, 1, 1, 1,-1,-1,-1,-1},
  { 1, 1,-1,-1, 1,-1, 1,-1},
  { 1, 1, 1,-1,-1, 1, 1, 1},
  { 1, 1, 1, 1,-1,-1,-1,-1},
  { 1, 1,-1, 1, 1, 1,-1, 1},
  { 1, 1, 1,-1,-1, 1, 1, 1},
  { 1, 1,-1,-1, 1,-1, 1,-1},
  { 1, 1,-1, 1, 1, 1,-1, 1}};

// ---------------------------------------------------------------------------
// Prep: fold sign table into weights, convert to fp16.
// W input layout: [8(j)][16(cout)][16(cin)][3][3]
// Output: d_Wg[tap][cout*8+m][cin*8+k]
// ---------------------------------------------------------------------------
__global__ void weff_kernel(const float* __restrict__ W) {
  int idx = blockIdx.x * 256 + threadIdx.x;
  if (idx >= 9 * 128 * 128) return;
  int ci  = idx & 127;
  int co  = (idx >> 7) & 127;
  int tap = idx >> 14;
  int cin = ci >> 3, k = ci & 7;
  int cout = co >> 3, m = co & 7;
  int j = cJ[m][k];
  float v = cS[m][k] * W[((j * 16 + cout) * 16 + cin) * 9 + tap];
  d_Wg[idx] = __float2half(v);
}

__global__ void beff_kernel(const float* __restrict__ b) {
  int co = threadIdx.x;             // 0..127
  int cout = co >> 3, m = co & 7;
  float s = 0.f;
#pragma unroll
  for (int k = 0; k < 8; k++) s += cS[m][k] * b[cJ[m][k] * 16 + cout];
  d_Beff[co] = s;
}

// ---------------------------------------------------------------------------
// Implicit-GEMM conv. One CTA per (b, h): 128 spatial (w) x 128 cout tile.
// 8 warps = 2 (M) x 4 (N). Warp tile 64x32 via m16n8k16 fp16 MMA, fp32 accum.
// K loop: 8 chunks of 16 input channels x 9 taps.
// ---------------------------------------------------------------------------
#define SAW 24                       // padded cin stride (48B rows: ldmatrix conflict-free)
#define SA_HALVES (3 * 130 * SAW)    // 9360 halves
#define SB_U32    (9 * 128 * 8)      // 9216 u32 = 18432 halves
#define SMEM_BYTES ((SA_HALVES * 2) + (SB_U32 * 4))   // 55584 B

__global__ void __launch_bounds__(256, 2)
conv_kernel(const float* __restrict__ x, float* __restrict__ out) {
  extern __shared__ __align__(16) __half sh[];
  __half*   sA   = sh;                               // [3][130][SAW]
  uint32_t* sB32 = (uint32_t*)(sh + SA_HALVES);      // [tap][co][8] (16 halves / row)

  const int h = blockIdx.x, b = blockIdx.y;
  const int tid  = threadIdx.x;
  const int lane = tid & 31, warp = tid >> 5;
  const int warpM = warp >> 2, warpN = warp & 3;
  const int g = lane >> 2;      // 0..7
  const int q = lane & 3;       // 0..3
  const int rsel = lane & 15, csel = lane >> 4;      // ldmatrix addressing

  const float* xb = x + (size_t)b * CH * HW * HW;
  const uint32_t* wg32 = (const uint32_t*)d_Wg;

  float acc[4][4][4];
#pragma unroll
  for (int i = 0; i < 4; i++)
#pragma unroll
    for (int j = 0; j < 4; j++)
#pragma unroll
      for (int t = 0; t < 4; t++) acc[i][j][t] = 0.f;

  // Zero halo columns (scol 0 and 129) once; main loads never touch them.
  if (tid < 96) {
    int r = tid / 32, ci = (tid & 31) >> 1, e = tid & 1;
    sA[(r * 130 + (e ? 129 : 0)) * SAW + ci] = __ushort_as_half(0);
  }

  for (int c0 = 0; c0 < CH; c0 += 16) {
    __syncthreads();   // protect previous iteration's smem reads (and the zeroing)

    // ---- load input chunk: 3 rows x 16 ch x 128 w, fp32 -> fp16 transpose ----
    // warp-iteration t: r = t/16; sub = t%16 -> ciBlock (2 x 8ch), wBlock (8 x 16w)
    // lane: g = ci-sub (8), q = w-quad (4 floats each). 2-way max smem store conflict.
#pragma unroll
    for (int it = 0; it < 6; ++it) {
      int t = warp + it * 8;              // 0..47
      int r = t / 16;
      int sub = t & 15;
      int ci = (sub & 1) * 8 + g;
      int w0 = (sub >> 1) * 16 + q * 4;
      int gh = h + r - 1;
      float4 v = make_float4(0.f, 0.f, 0.f, 0.f);
      if (gh >= 0 && gh < HW)
        v = *(const float4*)(xb + ((size_t)(c0 + ci) * HW + gh) * HW + w0);
      __half* p = sA + (r * 130 + w0 + 1) * SAW + ci;
      p[0]        = __float2half(v.x);
      p[SAW]      = __float2half(v.y);
      p[2 * SAW]  = __float2half(v.z);
      p[3 * SAW]  = __float2half(v.w);
    }

    // ---- load weight chunk: 9 taps x 128 co x 16 ci (L2-hot) ----
    {
      int cb = c0 >> 1;
      for (int i = tid; i < SB_U32; i += 256) {
        int off = i & 7;
        int co  = (i >> 3) & 127;
        int tap = i >> 10;
        sB32[i] = wg32[(tap * 128 + co) * 64 + cb + off];
      }
    }
    __syncthreads();

    // ---- MMA over 9 taps ----
#pragma unroll
    for (int tap = 0; tap < 9; ++tap) {
      const int dh = tap / 3, dw = tap % 3;

      uint32_t a[4][4];
#pragma unroll
      for (int mf = 0; mf < 4; ++mf) {
        int scol = warpM * 64 + mf * 16 + dw + rsel;   // = w + dw, input col w+dw-1
        uint32_t addr = (uint32_t)__cvta_generic_to_shared(
                            sA + (dh * 130 + scol) * SAW) + csel * 16;
        asm volatile(
          "ldmatrix.sync.aligned.m8n8.x4.shared.b16 {%0,%1,%2,%3}, [%4];\n"
          : "=r"(a[mf][0]), "=r"(a[mf][1]), "=r"(a[mf][2]), "=r"(a[mf][3])
          : "r"(addr));
      }

      uint32_t bb[4][2];
      const uint32_t* sbt = sB32 + tap * 1024 + (warpN * 32 + g) * 8;
#pragma unroll
      for (int nf = 0; nf < 4; ++nf) {
        const uint32_t* bp = sbt + nf * 64;
        bb[nf][0] = bp[q];
        bb[nf][1] = bp[q + 4];
      }

#pragma unroll
      for (int mf = 0; mf < 4; ++mf)
#pragma unroll
        for (int nf = 0; nf < 4; ++nf)
          asm volatile(
            "mma.sync.aligned.m16n8k16.row.col.f32.f16.f16.f32 "
            "{%0,%1,%2,%3}, {%4,%5,%6,%7}, {%8,%9}, {%0,%1,%2,%3};\n"
            : "+f"(acc[mf][nf][0]), "+f"(acc[mf][nf][1]),
              "+f"(acc[mf][nf][2]), "+f"(acc[mf][nf][3])
            : "r"(a[mf][0]), "r"(a[mf][1]), "r"(a[mf][2]), "r"(a[mf][3]),
              "r"(bb[nf][0]), "r"(bb[nf][1]));
    }
  }

  // ---- epilogue: add bias, store fp32 ----
  float* ob = out + (size_t)b * CH * HW * HW + h * HW;
#pragma unroll
  for (int mf = 0; mf < 4; ++mf) {
    int w0 = warpM * 64 + mf * 16 + (lane >> 2);
#pragma unroll
    for (int nf = 0; nf < 4; ++nf) {
      int co = warpN * 32 + nf * 8 + 2 * (lane & 3);
      float b0 = d_Beff[co], b1 = d_Beff[co + 1];
      ob[(size_t)co * HW * HW + w0]           = acc[mf][nf][0] + b0;
      ob[(size_t)(co + 1) * HW * HW + w0]     = acc[mf][nf][1] + b1;
      ob[(size_t)co * HW * HW + w0 + 8]       = acc[mf][nf][2] + b0;
      ob[(size_t)(co + 1) * HW * HW + w0 + 8] = acc[mf][nf][3] + b1;
    }
  }
}

// ---------------------------------------------------------------------------
extern "C" void kernel_launch(void* const* d_in, const int* in_sizes, int n_in,
                              void* d_out, int out_size) {
  (void)in_sizes; (void)n_in; (void)out_size;
  const float* x = (const float*)d_in[0];
  const float* W = (const float*)d_in[1];
  const float* b = (const float*)d_in[2];
  float* out = (float*)d_out;

  weff_kernel<<<(9 * 128 * 128 + 255) / 256, 256>>>(W);
  beff_kernel<<<1, 128>>>(b);

  cudaFuncSetAttribute(conv_kernel,
                       cudaFuncAttributeMaxDynamicSharedMemorySize, SMEM_BYTES);
  dim3 grid(HW, 8);   // (h, b)
  conv_kernel<<<grid, 256, SMEM_BYTES>>>(x, out);
}

// round 3
// speedup vs baseline: 1.0598x; 1.0598x over previous
#include <cuda_runtime.h>
#include <cuda_fp16.h>
#include <cstdint>

#define HW 128
#define CH 128
#define NB 8

// ---------------------------------------------------------------------------
// Device-global scratch
// ---------------------------------------------------------------------------
__device__ __align__(256) __half d_x16[(size_t)NB * HW * HW * CH];  // NHWC fp16, 33.5MB
__device__ __align__(256) __half d_Wg[9 * 128 * 128];               // [tap][co][ci]
__device__ float d_Beff[128];

__constant__ int cJ[8][8] = {
  {0,1,2,3,4,5,6,7},{1,0,4,6,2,7,3,5},{2,4,0,5,1,3,7,6},{3,6,5,0,7,2,1,4},
  {4,2,1,7,0,6,5,3},{5,7,3,2,6,0,4,1},{6,3,7,1,5,4,0,2},{7,5,6,4,3,1,2,0}};
__constant__ float cS[8][8] = {
  { 1, 1, 1, 1,-1,-1,-1,-1},{ 1, 1,-1,-1, 1,-1, 1,-1},
  { 1, 1, 1,-1,-1, 1, 1, 1},{ 1, 1, 1, 1,-1,-1,-1,-1},
  { 1, 1,-1, 1, 1, 1,-1, 1},{ 1, 1, 1,-1,-1, 1, 1, 1},
  { 1, 1,-1,-1, 1,-1, 1,-1},{ 1, 1,-1, 1, 1, 1,-1, 1}};

__device__ __forceinline__ uint32_t smem_u32(const void* p) {
  uint32_t a;
  asm("{ .reg .u64 t; cvta.to.shared.u64 t, %1; cvt.u32.u64 %0, t; }"
      : "=r"(a) : "l"(p));
  return a;
}
__device__ __forceinline__ void cp16(uint32_t dst, const void* src) {
  asm volatile("cp.async.cg.shared.global [%0], [%1], 16;"
               :: "r"(dst), "l"(src) : "memory");
}
__device__ __forceinline__ void cp_commit() {
  asm volatile("cp.async.commit_group;" ::: "memory");
}
__device__ __forceinline__ void cp_wait1() {
  asm volatile("cp.async.wait_group 1;" ::: "memory");
}
__device__ __forceinline__ void cp_wait0() {
  asm volatile("cp.async.wait_group 0;" ::: "memory");
}

// ---------------------------------------------------------------------------
// Prepass 1: fp32 NCHW -> fp16 NHWC. One CTA per (h, b).
// ---------------------------------------------------------------------------
__global__ void __launch_bounds__(256) xprep_kernel(const float* __restrict__ x) {
  __shared__ __align__(16) __half sm[128 * 136];
  const int h = blockIdx.x, b = blockIdx.y, tid = threadIdx.x;
  const float* xp = x + ((size_t)b * CH) * HW * HW + (size_t)h * HW;
#pragma unroll
  for (int i = 0; i < 16; ++i) {
    int idx = tid + i * 256;          // ci = idx&127, wq = idx>>7 (0..31)
    int ci = idx & 127, wq = idx >> 7;
    float4 v = *(const float4*)(xp + (size_t)ci * HW * HW + wq * 4);
    sm[(wq * 4 + 0) * 136 + ci] = __float2half(v.x);
    sm[(wq * 4 + 1) * 136 + ci] = __float2half(v.y);
    sm[(wq * 4 + 2) * 136 + ci] = __float2half(v.z);
    sm[(wq * 4 + 3) * 136 + ci] = __float2half(v.w);
  }
  __syncthreads();
  __half* op = d_x16 + ((size_t)(b * HW + h)) * HW * CH;
#pragma unroll
  for (int i = 0; i < 8; ++i) {
    int idx = tid + i * 256;          // w = idx>>4, c8 = idx&15
    int w = idx >> 4, c8 = idx & 15;
    uint4 u = *(const uint4*)(sm + w * 136 + c8 * 8);
    *(uint4*)(op + w * CH + c8 * 8) = u;
  }
}

// ---------------------------------------------------------------------------
// Prepass 2: fold signs into weights -> d_Wg[tap][co][ci] fp16.
// ---------------------------------------------------------------------------
__global__ void __launch_bounds__(256) weff_kernel(const float* __restrict__ W) {
  int idx = blockIdx.x * 256 + threadIdx.x;
  if (idx >= 9 * 128 * 128) return;
  int ci = idx & 127;
  int co = (idx >> 7) & 127;
  int tap = idx >> 14;
  int cin = ci >> 3, k = ci & 7;
  int cout = co >> 3, m = co & 7;
  float v = cS[m][k] * W[((cJ[m][k] * 16 + cout) * 16 + cin) * 9 + tap];
  d_Wg[idx] = __float2half(v);
}

__global__ void beff_kernel(const float* __restrict__ b) {
  int co = threadIdx.x;
  int cout = co >> 3, m = co & 7;
  float s = 0.f;
#pragma unroll
  for (int k = 0; k < 8; k++) s += cS[m][k] * b[cJ[m][k] * 16 + cout];
  d_Beff[co] = s;
}

// ---------------------------------------------------------------------------
// Conv kernel. 1 CTA per (b, 2 output rows). M=256 (2 h-rows x 128 w),
// N=128 cout, K = 9 taps x 128 ci, chunked 16 ci. 8 warps of 64x64.
// Double-buffered cp.async for A (4 rows x 130 w x 16ci) and B (9x128x16).
// ---------------------------------------------------------------------------
#define SAW 24                         // halves per (r,w) slot (48B, conflict-free)
#define AROW 132                       // w slots per row r
#define A_BYTES (4 * AROW * SAW * 2)   // 25344
#define B_BYTES (9 * 128 * 32)         // 36864
#define SM_TOTAL (2 * A_BYTES + 2 * B_BYTES)   // 124416

__global__ void __launch_bounds__(256, 1)
conv_kernel(float* __restrict__ out) {
  extern __shared__ __align__(128) unsigned char sh[];
  const uint32_t sA0 = smem_u32(sh);
  const uint32_t sB0 = sA0 + 2 * A_BYTES;
  uint32_t* sB32base = (uint32_t*)(sh + 2 * A_BYTES);

  const int tid = threadIdx.x, warp = tid >> 5, lane = tid & 31;
  const int h2 = blockIdx.x, b = blockIdx.y;
  const int h0 = h2 * 2;
  const int warpM = warp >> 1, warpN = warp & 1;
  const int hh = warpM >> 1, wq0 = (warpM & 1) * 64;
  const int g = lane >> 2, q = lane & 3;
  const int rsel = lane & 15, csel = lane >> 4;

  // zero both A buffers (covers w-halo slots and invalid h rows; valid slots
  // get fully overwritten by cp.async each chunk)
  {
    uint4 z = make_uint4(0, 0, 0, 0);
    uint4* p = (uint4*)sh;
    for (int i = tid; i < 2 * A_BYTES / 16; i += 256) p[i] = z;
  }
  __syncthreads();

  float acc[4][8][4];
#pragma unroll
  for (int i = 0; i < 4; i++)
#pragma unroll
    for (int j = 0; j < 8; j++)
#pragma unroll
      for (int t = 0; t < 4; t++) acc[i][j][t] = 0.f;

  // ---- chunk issue (A + B) ----
  auto issue = [&](int c0, int buf) {
    uint32_t aB = sA0 + buf * A_BYTES;
#pragma unroll
    for (int i = 0; i < 4; ++i) {
      int task = tid + i * 256;              // r(2b) | w(7b) | half(1b)
      int r = task >> 8;
      int w = (task >> 1) & 127;
      int half = task & 1;
      int gh = h0 - 1 + r;
      if ((unsigned)gh < (unsigned)HW) {
        const __half* src = d_x16 +
            (((size_t)(b * HW + gh) * HW + w) * CH + c0 + half * 8);
        cp16(aB + (uint32_t)(r * AROW + w + 1) * 48 + half * 16, src);
      }
    }
    uint32_t bB = sB0 + buf * B_BYTES;
#pragma unroll
    for (int i = 0; i < 9; ++i) {
      int idx = tid + i * 256;               // tap(0..8) | co(7b) | half(1b)
      int tap = idx >> 8;
      int co = (idx >> 1) & 127;
      int half = idx & 1;
      const __half* src = d_Wg + ((tap * 128 + co) * 128 + c0) + half * 8;
      cp16(bB + (uint32_t)(tap * 128 + co) * 32 + half * 16, src);
    }
    cp_commit();
  };

  issue(0, 0);

  for (int c = 0; c < 8; ++c) {
    if (c < 7) issue((c + 1) * 16, (c + 1) & 1);
    if (c < 7) cp_wait1(); else cp_wait0();
    __syncthreads();

    const int buf = c & 1;
    const uint32_t aB = sA0 + buf * A_BYTES;
    const uint32_t* sBp = sB32base + buf * (B_BYTES / 4);

#pragma unroll
    for (int tap = 0; tap < 9; ++tap) {
      const int dh = tap / 3, dw = tap % 3;
      uint32_t a[4][4];
      uint32_t arow = aB + (uint32_t)((hh + dh) * AROW) * 48;
#pragma unroll
      for (int mf = 0; mf < 4; ++mf) {
        uint32_t addr = arow + (uint32_t)(wq0 + mf * 16 + dw + rsel) * 48
                        + csel * 16;
        asm volatile(
          "ldmatrix.sync.aligned.m8n8.x4.shared.b16 {%0,%1,%2,%3}, [%4];\n"
          : "=r"(a[mf][0]), "=r"(a[mf][1]), "=r"(a[mf][2]), "=r"(a[mf][3])
          : "r"(addr));
      }
      const uint32_t* sbt = sBp + tap * 1024 + (warpN * 64 + g) * 8;
#pragma unroll
      for (int nf = 0; nf < 8; ++nf) {
        const uint32_t* bp = sbt + nf * 64;
        uint32_t b0 = bp[q], b1 = bp[q + 4];
#pragma unroll
        for (int mf = 0; mf < 4; ++mf)
          asm volatile(
            "mma.sync.aligned.m16n8k16.row.col.f32.f16.f16.f32 "
            "{%0,%1,%2,%3}, {%4,%5,%6,%7}, {%8,%9}, {%0,%1,%2,%3};\n"
            : "+f"(acc[mf][nf][0]), "+f"(acc[mf][nf][1]),
              "+f"(acc[mf][nf][2]), "+f"(acc[mf][nf][3])
            : "r"(a[mf][0]), "r"(a[mf][1]), "r"(a[mf][2]), "r"(a[mf][3]),
              "r"(b0), "r"(b1));
      }
    }
    __syncthreads();
  }

  // ---- epilogue: bias + direct stores ----
  const int h_out = h0 + hh;
  float* ob = out + ((size_t)(b * CH) * HW + h_out) * HW;
#pragma unroll
  for (int nf = 0; nf < 8; ++nf) {
    int co = warpN * 64 + nf * 8 + 2 * q;
    float b0 = d_Beff[co], b1 = d_Beff[co + 1];
    float* p0 = ob + (size_t)co * HW * HW;
    float* p1 = p0 + (size_t)HW * HW;
#pragma unroll
    for (int mf = 0; mf < 4; ++mf) {
      int w = wq0 + mf * 16 + g;
      p0[w]     = acc[mf][nf][0] + b0;
      p1[w]     = acc[mf][nf][1] + b1;
      p0[w + 8] = acc[mf][nf][2] + b0;
      p1[w + 8] = acc[mf][nf][3] + b1;
    }
  }
}

// ---------------------------------------------------------------------------
extern "C" void kernel_launch(void* const* d_in, const int* in_sizes, int n_in,
                              void* d_out, int out_size) {
  (void)in_sizes; (void)n_in; (void)out_size;
  const float* x = (const float*)d_in[0];
  const float* W = (const float*)d_in[1];
  const float* b = (const float*)d_in[2];
  float* out = (float*)d_out;

  dim3 gx(HW, NB);
  xprep_kernel<<<gx, 256>>>(x);
  weff_kernel<<<(9 * 128 * 128 + 255) / 256, 256>>>(W);
  beff_kernel<<<1, 128>>>(b);

  cudaFuncSetAttribute(conv_kernel,
                       cudaFuncAttributeMaxDynamicSharedMemorySize, SM_TOTAL);
  dim3 grid(HW / 2, NB);
  conv_kernel<<<grid, 256, SM_TOTAL>>>(out);
}